// round 16
// baseline (speedup 1.0000x reference)
#include <cuda_runtime.h>
#include <math_constants.h>

// FusedScaleMaskSoftmax: x[2,16,2048,2048] fp32 -> causal-masked softmax (last dim).
//
// R15 = R14 (best: 117.34us) + two micro-tunes:
//  - Kernel B: full-chunk fast path. Only ~1 of 257 chunks per row pair is
//    partial; full chunks (b+8 <= L) now take an unguarded exp2 path, removing
//    ~16 ISETP/SEL ops per chunk from the dependent chain. Masked path kept
//    for the boundary chunk (exact 0s in masked lanes).
//  - Kernel A: 512-thread CTAs (8 pairs/CTA, 4096 blocks) - fewer, fatter
//    pure-store CTAs for the PDL backfill window.
// Structure unchanged: B (softmax over causal prefix) is PDL primary and
// triggers completion at entry; A (split-pair balanced zero-fill of masked
// tails) launches with programmatic stream serialization and backfills B's
// partial-last-wave drain. Chunk coverage exact + disjoint.

#define SK        2048
#define THREADS_B 256            // 8 warps = 8 rows per CTA (kernel B)
#define WARPS_PB  (THREADS_B / 32)
#define THREADS_A 512            // 16 warps = 8 pairs per CTA (kernel A)
#define PAIRS_PC  (THREADS_A / 64)
#define NC        8              // 256-bit chunks per lane in kernel B
#define NA        4              // zero-fill iters in kernel A (ceil(128/32))

__device__ __forceinline__ float ex2_approx(float x) {
    float r;
    asm("ex2.approx.ftz.f32 %0, %1;" : "=f"(r) : "f"(x));
    return r;
}

__device__ __forceinline__ void ldg256_cs(const float* p, float* v) {
    unsigned u0, u1, u2, u3, u4, u5, u6, u7;
    asm volatile("ld.global.cs.v8.b32 {%0,%1,%2,%3,%4,%5,%6,%7}, [%8];"
        : "=r"(u0), "=r"(u1), "=r"(u2), "=r"(u3),
          "=r"(u4), "=r"(u5), "=r"(u6), "=r"(u7)
        : "l"(p));
    v[0] = __uint_as_float(u0); v[1] = __uint_as_float(u1);
    v[2] = __uint_as_float(u2); v[3] = __uint_as_float(u3);
    v[4] = __uint_as_float(u4); v[5] = __uint_as_float(u5);
    v[6] = __uint_as_float(u6); v[7] = __uint_as_float(u7);
}

__device__ __forceinline__ void stg256(float* p, const float* v) {
    asm volatile("st.global.v8.b32 [%0], {%1,%2,%3,%4,%5,%6,%7,%8};"
        :: "l"(p),
           "r"(__float_as_uint(v[0])), "r"(__float_as_uint(v[1])),
           "r"(__float_as_uint(v[2])), "r"(__float_as_uint(v[3])),
           "r"(__float_as_uint(v[4])), "r"(__float_as_uint(v[5])),
           "r"(__float_as_uint(v[6])), "r"(__float_as_uint(v[7]))
        : "memory");
}

// Balanced row mapping: pair j with 2047-j within each 2048-row matrix.
__device__ __forceinline__ unsigned map_row(unsigned g) {
    const unsigned q = g & (SK - 1);
    const unsigned j = q >> 1;
    const unsigned r = (q & 1u) ? (SK - 1 - j) : j;
    return (g & ~(unsigned)(SK - 1)) | r;
}

// ---------------- Kernel A: zero-fill of masked tails (PDL secondary) ----------
// Split-pair balanced: pair (j, 2047-j) has exactly 255 tail chunks; the
// pair's two warps write ~half each (warp0: virtual [0,128), warp1: [128,255)).
__global__ __launch_bounds__(THREADS_A)
void causal_zero_tail(float* __restrict__ out) {
    const int wid = threadIdx.x >> 5;
    const int lid = threadIdx.x & 31;

    const unsigned P = blockIdx.x * PAIRS_PC + (wid >> 1); // pair id
    const int h = wid & 1;

    const unsigned m = P >> 10;            // matrix 0..31
    const int j = (int)(P & 1023u);
    const unsigned rowL = (m << 11) + j;
    const unsigned rowH = (m << 11) + (SK - 1 - j);
    const int CL = (j >> 3) + 1;           // first masked chunk of rowL
    const int CH = 256 - (j >> 3);         // first masked chunk of rowH
    const int TA = 256 - CL;               // tail chunks of rowL
    const int T  = 255;                    // total tails per pair (constant)
    const int S  = 128;
    const int u0 = h ? S : 0;
    const int u1 = h ? T : S;

    float* __restrict__ yL = out + (size_t)rowL * SK;
    float* __restrict__ yH = out + (size_t)rowH * SK;
    const float z[8] = {0.f, 0.f, 0.f, 0.f, 0.f, 0.f, 0.f, 0.f};

    #pragma unroll
    for (int it = 0; it < NA; it++) {
        const int u = u0 + it * 32 + lid;
        if (u < u1) {
            const bool isL = (u < TA);
            const int  c   = isL ? (CL + u) : (CH + (u - TA));
            stg256((isL ? yL : yH) + (c << 3), z);
        }
    }
}

// ---------------- Kernel B: softmax over the causal prefix (PDL primary) ------
__global__ __launch_bounds__(THREADS_B)
void causal_softmax_prefix(const float* __restrict__ x,
                           float* __restrict__ out) {
    // Nothing in kernel A depends on B's output: release the PDL gate now.
    cudaTriggerProgrammaticLaunchCompletion();

    // SCALE * log2(e): fold 1/sqrt(128) into the exp2 argument.
    const float C = 0.08838834764831845f * 1.4426950408889634f;

    const int wid = threadIdx.x >> 5;
    const int lid = threadIdx.x & 31;

    const unsigned g   = blockIdx.x * WARPS_PB + wid;
    const unsigned row = map_row(g);
    const int L = (int)(row & (SK - 1)) + 1;

    const size_t base_elem = (size_t)row * SK;
    const float* __restrict__ xrow = x   + base_elem;
    float* __restrict__       yrow = out + base_elem;

    float v[NC][8];

    // Front-batched 256-bit loads of valid chunks (8c < L).
    #pragma unroll
    for (int k = 0; k < NC; k++) {
        const int b = (lid + k * 32) << 3;
        if (b < L) ldg256_cs(xrow + b, v[k]);
    }

    // exp2(x*C): fast path for fully-valid chunks, masked path only for the
    // single boundary chunk (masked lanes -> exact 0).
    float s = 0.0f;
    #pragma unroll
    for (int k = 0; k < NC; k++) {
        const int b = (lid + k * 32) << 3;
        if (b + 8 <= L) {
            float a[8];
            #pragma unroll
            for (int e = 0; e < 8; e++)
                a[e] = ex2_approx(v[k][e] * C);
            #pragma unroll
            for (int e = 0; e < 8; e++)
                v[k][e] = a[e];
            s += ((a[0] + a[1]) + (a[2] + a[3]))
               + ((a[4] + a[5]) + (a[6] + a[7]));
        } else if (b < L) {
            float a[8];
            #pragma unroll
            for (int e = 0; e < 8; e++)
                a[e] = (b + e < L) ? ex2_approx(v[k][e] * C) : 0.0f;
            #pragma unroll
            for (int e = 0; e < 8; e++)
                v[k][e] = a[e];
            s += ((a[0] + a[1]) + (a[2] + a[3]))
               + ((a[4] + a[5]) + (a[6] + a[7]));
        }
    }

    // Warp sum-reduce (no barriers).
    #pragma unroll
    for (int o = 16; o > 0; o >>= 1)
        s += __shfl_xor_sync(0xffffffffu, s, o);

    float inv;
    asm("rcp.approx.ftz.f32 %0, %1;" : "=f"(inv) : "f"(s));

    // Normalize + 256-bit store of valid chunks only.
    #pragma unroll
    for (int k = 0; k < NC; k++) {
        const int b = (lid + k * 32) << 3;
        if (b < L) {
            float o[8];
            #pragma unroll
            for (int e = 0; e < 8; e++)
                o[e] = v[k][e] * inv;
            stg256(yrow + b, o);
        }
    }
}

extern "C" void kernel_launch(void* const* d_in, const int* in_sizes, int n_in,
                              void* d_out, int out_size) {
    const float* x = (const float*)d_in[0];
    float* out = (float*)d_out;

    const int rows     = out_size / SK;            // 65536
    const int blocks_b = rows / WARPS_PB;          // 8192
    const int blocks_a = (rows / 2) / PAIRS_PC;    // 4096

    // Primary: softmax over valid chunks. Triggers PDL at entry.
    causal_softmax_prefix<<<blocks_b, THREADS_B>>>(x, out);

    // Secondary: zero-fill of masked tails, backfills primary's drain.
    cudaLaunchAttribute attrs[1];
    attrs[0].id = cudaLaunchAttributeProgrammaticStreamSerialization;
    attrs[0].val.programmaticStreamSerializationAllowed = 1;

    cudaLaunchConfig_t cfg = {};
    cfg.gridDim  = dim3(blocks_a, 1, 1);
    cfg.blockDim = dim3(THREADS_A, 1, 1);
    cfg.dynamicSmemBytes = 0;
    cfg.stream = 0;
    cfg.attrs = attrs;
    cfg.numAttrs = 1;

    cudaLaunchKernelEx(&cfg, causal_zero_tail, out);
}

// round 17
// speedup vs baseline: 1.0055x; 1.0055x over previous
#include <cuda_runtime.h>
#include <math_constants.h>

// FusedScaleMaskSoftmax: x[2,16,2048,2048] fp32 -> causal-masked softmax (last dim).
//
// R16: best-of-each composition at the bandwidth floor (768MB compulsory
// traffic @ ~6.55TB/s measured LTS cap):
//   Kernel B (PDL primary)  : one row per warp, balanced row pairing, 256-bit
//     ld/st, zero barriers, full-chunk fast path for the exp2 stage (R15).
//   Kernel A (PDL secondary): split-pair balanced zero-fill, 256-thread CTAs
//     (R14 measured best; R15's 512-thr variant slipped 0.13us), with .cs
//     zero stores - these lines are dead on arrival, evict-first keeps them
//     from displacing B's in-flight dirty lines during the overlap window.
// PDL: B triggers completion at entry; A backfills B's partial-last-wave
// drain. Chunk coverage exact + disjoint (B: c < ceil(L/8), A: c >= ceil(L/8)).

#define SK        2048
#define THREADS   256            // 8 warps per CTA (both kernels)
#define WARPS_PB  (THREADS / 32)
#define PAIRS_PC  4              // pairs per CTA in kernel A
#define NC        8              // 256-bit chunks per lane in kernel B
#define NA        4              // zero-fill iters in kernel A (ceil(128/32))

__device__ __forceinline__ float ex2_approx(float x) {
    float r;
    asm("ex2.approx.ftz.f32 %0, %1;" : "=f"(r) : "f"(x));
    return r;
}

__device__ __forceinline__ void ldg256_cs(const float* p, float* v) {
    unsigned u0, u1, u2, u3, u4, u5, u6, u7;
    asm volatile("ld.global.cs.v8.b32 {%0,%1,%2,%3,%4,%5,%6,%7}, [%8];"
        : "=r"(u0), "=r"(u1), "=r"(u2), "=r"(u3),
          "=r"(u4), "=r"(u5), "=r"(u6), "=r"(u7)
        : "l"(p));
    v[0] = __uint_as_float(u0); v[1] = __uint_as_float(u1);
    v[2] = __uint_as_float(u2); v[3] = __uint_as_float(u3);
    v[4] = __uint_as_float(u4); v[5] = __uint_as_float(u5);
    v[6] = __uint_as_float(u6); v[7] = __uint_as_float(u7);
}

// Default write-back stores (kernel B results: normal policy measured best).
__device__ __forceinline__ void stg256(float* p, const float* v) {
    asm volatile("st.global.v8.b32 [%0], {%1,%2,%3,%4,%5,%6,%7,%8};"
        :: "l"(p),
           "r"(__float_as_uint(v[0])), "r"(__float_as_uint(v[1])),
           "r"(__float_as_uint(v[2])), "r"(__float_as_uint(v[3])),
           "r"(__float_as_uint(v[4])), "r"(__float_as_uint(v[5])),
           "r"(__float_as_uint(v[6])), "r"(__float_as_uint(v[7]))
        : "memory");
}

// Evict-first streaming stores (kernel A zeros: dead-on-arrival lines).
__device__ __forceinline__ void stg256_cs(float* p, const float* v) {
    asm volatile("st.global.cs.v8.b32 [%0], {%1,%2,%3,%4,%5,%6,%7,%8};"
        :: "l"(p),
           "r"(__float_as_uint(v[0])), "r"(__float_as_uint(v[1])),
           "r"(__float_as_uint(v[2])), "r"(__float_as_uint(v[3])),
           "r"(__float_as_uint(v[4])), "r"(__float_as_uint(v[5])),
           "r"(__float_as_uint(v[6])), "r"(__float_as_uint(v[7]))
        : "memory");
}

// Balanced row mapping: pair j with 2047-j within each 2048-row matrix.
__device__ __forceinline__ unsigned map_row(unsigned g) {
    const unsigned q = g & (SK - 1);
    const unsigned j = q >> 1;
    const unsigned r = (q & 1u) ? (SK - 1 - j) : j;
    return (g & ~(unsigned)(SK - 1)) | r;
}

// ---------------- Kernel A: zero-fill of masked tails (PDL secondary) ----------
// Split-pair balanced: pair (j, 2047-j) has exactly 255 tail chunks; the
// pair's two warps write ~half each (warp0: virtual [0,128), warp1: [128,255)).
__global__ __launch_bounds__(THREADS)
void causal_zero_tail(float* __restrict__ out) {
    const int wid = threadIdx.x >> 5;
    const int lid = threadIdx.x & 31;

    const unsigned P = blockIdx.x * PAIRS_PC + (wid >> 1); // pair id
    const int h = wid & 1;

    const unsigned m = P >> 10;            // matrix 0..31
    const int j = (int)(P & 1023u);
    const unsigned rowL = (m << 11) + j;
    const unsigned rowH = (m << 11) + (SK - 1 - j);
    const int CL = (j >> 3) + 1;           // first masked chunk of rowL
    const int CH = 256 - (j >> 3);         // first masked chunk of rowH
    const int TA = 256 - CL;               // tail chunks of rowL
    const int T  = 255;                    // total tails per pair (constant)
    const int S  = 128;
    const int u0 = h ? S : 0;
    const int u1 = h ? T : S;

    float* __restrict__ yL = out + (size_t)rowL * SK;
    float* __restrict__ yH = out + (size_t)rowH * SK;
    const float z[8] = {0.f, 0.f, 0.f, 0.f, 0.f, 0.f, 0.f, 0.f};

    #pragma unroll
    for (int it = 0; it < NA; it++) {
        const int u = u0 + it * 32 + lid;
        if (u < u1) {
            const bool isL = (u < TA);
            const int  c   = isL ? (CL + u) : (CH + (u - TA));
            stg256_cs((isL ? yL : yH) + (c << 3), z);
        }
    }
}

// ---------------- Kernel B: softmax over the causal prefix (PDL primary) ------
__global__ __launch_bounds__(THREADS)
void causal_softmax_prefix(const float* __restrict__ x,
                           float* __restrict__ out) {
    // Nothing in kernel A depends on B's output: release the PDL gate now.
    cudaTriggerProgrammaticLaunchCompletion();

    // SCALE * log2(e): fold 1/sqrt(128) into the exp2 argument.
    const float C = 0.08838834764831845f * 1.4426950408889634f;

    const int wid = threadIdx.x >> 5;
    const int lid = threadIdx.x & 31;

    const unsigned g   = blockIdx.x * WARPS_PB + wid;
    const unsigned row = map_row(g);
    const int L = (int)(row & (SK - 1)) + 1;

    const size_t base_elem = (size_t)row * SK;
    const float* __restrict__ xrow = x   + base_elem;
    float* __restrict__       yrow = out + base_elem;

    float v[NC][8];

    // Front-batched 256-bit loads of valid chunks (8c < L).
    #pragma unroll
    for (int k = 0; k < NC; k++) {
        const int b = (lid + k * 32) << 3;
        if (b < L) ldg256_cs(xrow + b, v[k]);
    }

    // exp2(x*C): unguarded fast path for fully-valid chunks; masked path only
    // for the single boundary chunk (masked lanes -> exact 0).
    float s = 0.0f;
    #pragma unroll
    for (int k = 0; k < NC; k++) {
        const int b = (lid + k * 32) << 3;
        if (b + 8 <= L) {
            float a[8];
            #pragma unroll
            for (int e = 0; e < 8; e++)
                a[e] = ex2_approx(v[k][e] * C);
            #pragma unroll
            for (int e = 0; e < 8; e++)
                v[k][e] = a[e];
            s += ((a[0] + a[1]) + (a[2] + a[3]))
               + ((a[4] + a[5]) + (a[6] + a[7]));
        } else if (b < L) {
            float a[8];
            #pragma unroll
            for (int e = 0; e < 8; e++)
                a[e] = (b + e < L) ? ex2_approx(v[k][e] * C) : 0.0f;
            #pragma unroll
            for (int e = 0; e < 8; e++)
                v[k][e] = a[e];
            s += ((a[0] + a[1]) + (a[2] + a[3]))
               + ((a[4] + a[5]) + (a[6] + a[7]));
        }
    }

    // Warp sum-reduce (no barriers).
    #pragma unroll
    for (int o = 16; o > 0; o >>= 1)
        s += __shfl_xor_sync(0xffffffffu, s, o);

    float inv;
    asm("rcp.approx.ftz.f32 %0, %1;" : "=f"(inv) : "f"(s));

    // Normalize + 256-bit store of valid chunks only.
    #pragma unroll
    for (int k = 0; k < NC; k++) {
        const int b = (lid + k * 32) << 3;
        if (b < L) {
            float o[8];
            #pragma unroll
            for (int e = 0; e < 8; e++)
                o[e] = v[k][e] * inv;
            stg256(yrow + b, o);
        }
    }
}

extern "C" void kernel_launch(void* const* d_in, const int* in_sizes, int n_in,
                              void* d_out, int out_size) {
    const float* x = (const float*)d_in[0];
    float* out = (float*)d_out;

    const int rows     = out_size / SK;            // 65536
    const int blocks_b = rows / WARPS_PB;          // 8192
    const int blocks_a = (rows / 2) / PAIRS_PC;    // 8192

    // Primary: softmax over valid chunks. Triggers PDL at entry.
    causal_softmax_prefix<<<blocks_b, THREADS>>>(x, out);

    // Secondary: zero-fill of masked tails, backfills primary's drain.
    cudaLaunchAttribute attrs[1];
    attrs[0].id = cudaLaunchAttributeProgrammaticStreamSerialization;
    attrs[0].val.programmaticStreamSerializationAllowed = 1;

    cudaLaunchConfig_t cfg = {};
    cfg.gridDim  = dim3(blocks_a, 1, 1);
    cfg.blockDim = dim3(THREADS, 1, 1);
    cfg.dynamicSmemBytes = 0;
    cfg.stream = 0;
    cfg.attrs = attrs;
    cfg.numAttrs = 1;

    cudaLaunchKernelEx(&cfg, causal_zero_tail, out);
}